// round 13
// baseline (speedup 1.0000x reference)
#include <cuda_runtime.h>
#include <cuda_fp16.h>
#include <cstdint>
#include <math.h>

#define SEQ 8192
#define DIN 512
#define D   64
#define BN  64
#define NSPLIT 16
#define TILES_PER_UNIT 8            // 8 * 64 = 512 keys per unit
#define TOTAL_UNITS (128 * NSPLIT)  // 2048
#define GRID_ATTN 456               // 3 CTAs x 152 SMs (GB300)
#define QK_SCALE 0.18033688011112042f   // 0.125 * log2(e)
#define XSB 40      // qkv smem row stride (halves)
#define KST 72      // attn smem row stride (halves)
#define BUFB (3 * 64 * KST * 2)     // one attn buffer: 27648 B (kh, kl, vh)
#define QLO_HALF (BUFB)             // Q-lo tile offset in halves
#define ATT_SMEM (2 * BUFB + 64 * KST * 2)   // 64512 B

// ---------------- device scratch (no cudaMalloc allowed) ----------------
__device__ __half g_wh[3][D * DIN], g_wl[3][D * DIN];   // W^T fp16 hi/lo
__device__ __half g_qh[SEQ * D], g_ql[SEQ * D];         // Q fp16 hi/lo (scaled)
__device__ __half g_kh[SEQ * D], g_kl[SEQ * D];         // K fp16 hi/lo
__device__ __half g_vh[D * SEQ];                        // V^T fp16 (single)
__device__ float g_po[NSPLIT][SEQ * D];
__device__ float g_pm[NSPLIT][SEQ];
__device__ float g_pl[NSPLIT][SEQ];
__device__ unsigned int g_ctr;                          // dynamic unit counter

// ---------------- helpers ----------------
__device__ __forceinline__ float ex2(float x) {
    float r; asm("ex2.approx.f32 %0, %1;" : "=f"(r) : "f"(x)); return r;
}
__device__ __forceinline__ void mma_f16(float* c, const uint32_t* a,
                                        uint32_t b0, uint32_t b1) {
    asm volatile(
        "mma.sync.aligned.m16n8k16.row.col.f32.f16.f16.f32 "
        "{%0,%1,%2,%3},{%4,%5,%6,%7},{%8,%9},{%0,%1,%2,%3};"
        : "+f"(c[0]), "+f"(c[1]), "+f"(c[2]), "+f"(c[3])
        : "r"(a[0]), "r"(a[1]), "r"(a[2]), "r"(a[3]), "r"(b0), "r"(b1));
}
// fp16-accumulator variant (kept for qkv correction passes)
__device__ __forceinline__ void mma_f16acc(uint32_t* c, const uint32_t* a,
                                           uint32_t b0, uint32_t b1) {
    asm volatile(
        "mma.sync.aligned.m16n8k16.row.col.f16.f16.f16.f16 "
        "{%0,%1},{%2,%3,%4,%5},{%6,%7},{%0,%1};"
        : "+r"(c[0]), "+r"(c[1])
        : "r"(a[0]), "r"(a[1]), "r"(a[2]), "r"(a[3]), "r"(b0), "r"(b1));
}
__device__ __forceinline__ void ldm_x4(uint32_t& r0, uint32_t& r1,
                                       uint32_t& r2, uint32_t& r3, uint32_t addr) {
    asm volatile("ldmatrix.sync.aligned.m8n8.x4.shared.b16 {%0,%1,%2,%3}, [%4];"
                 : "=r"(r0), "=r"(r1), "=r"(r2), "=r"(r3) : "r"(addr));
}
__device__ __forceinline__ uint32_t pack_f16(float lo, float hi) {
    uint32_t r;
    asm("cvt.rn.f16x2.f32 %0, %1, %2;" : "=r"(r) : "f"(hi), "f"(lo));
    return r;
}
// fp16 hi/lo split of pair (v0->low half, v1->high half)
__device__ __forceinline__ void fsplit2(float v0, float v1, uint32_t& h, uint32_t& l) {
    __half h0 = __float2half_rn(v0), h1 = __float2half_rn(v1);
    float l0 = v0 - __half2float(h0), l1 = v1 - __half2float(h1);
    __half2 hh(h0, h1);
    __half2 ll(__float2half_rn(l0), __float2half_rn(l1));
    h = *(uint32_t*)&hh;
    l = *(uint32_t*)&ll;
}
__device__ __forceinline__ uint32_t smem_u32(const void* p) {
    uint32_t a;
    asm("{ .reg .u64 t; cvta.to.shared.u64 t, %1; cvt.u32.u64 %0, t; }" : "=r"(a) : "l"(p));
    return a;
}
__device__ __forceinline__ void cp16(uint32_t dst, const void* src) {
    asm volatile("cp.async.cg.shared.global [%0], [%1], 16;" :: "r"(dst), "l"(src) : "memory");
}
#define CP_COMMIT() asm volatile("cp.async.commit_group;" ::: "memory")
#define CP_WAIT0()  asm volatile("cp.async.wait_group 0;" ::: "memory")
#define CP_WAIT1()  asm volatile("cp.async.wait_group 1;" ::: "memory")

// ---------------------------------------------------------------------------
// Kernel -1: reset dynamic counter (runs inside the graph each replay).
// ---------------------------------------------------------------------------
__global__ void zero_ctr_kernel() { g_ctr = 0u; }

// ---------------------------------------------------------------------------
// Kernel 0: split W^T into fp16 hi/lo.
// ---------------------------------------------------------------------------
__global__ void prep_kernel(const float* __restrict__ Wq,
                            const float* __restrict__ Wk,
                            const float* __restrict__ Wv) {
    int i = blockIdx.x * 256 + threadIdx.x;          // < 3*D*DIN
    int p = i / (D * DIN), r = i % (D * DIN);
    int n = r / DIN, k = r % DIN;
    const float* W = (p == 0) ? Wq : (p == 1) ? Wk : Wv;
    float w = W[k * D + n];
    __half h = __float2half_rn(w);
    g_wh[p][n * DIN + k] = h;
    g_wl[p][n * DIN + k] = __float2half_rn(w - __half2float(h));
}

// ---------------------------------------------------------------------------
// Kernel 1: QKV projection, fp16 2-split.  hh pass f32-accum; corrections
// (xl*Wh, xh*Wl) in f16-accum.  grid (SEQ/128, 3).
// ---------------------------------------------------------------------------
#define QKV_SMEM ((128 * XSB * 2 + 64 * XSB * 2) * 2)   // 30720 B

__global__ __launch_bounds__(256, 2) void qkv_kernel(const float* __restrict__ x) {
    extern __shared__ __half qsm[];
    __half* xh = qsm;                 // [128][XSB]
    __half* xl = xh + 128 * XSB;
    __half* wh = xl + 128 * XSB;      // [64][XSB]
    __half* wl = wh + 64 * XSB;

    const int tid = threadIdx.x, w = tid >> 5, lane = tid & 31;
    const int g = lane >> 2, t = lane & 3;
    const int r0 = blockIdx.x * 128;
    const int p = blockIdx.y;

    float c[8][4];
    uint32_t cc[8][2];
    #pragma unroll
    for (int nf = 0; nf < 8; nf++) {
        cc[nf][0] = 0u; cc[nf][1] = 0u;
        #pragma unroll
        for (int i = 0; i < 4; i++) c[nf][i] = 0.0f;
    }

    for (int kb = 0; kb < DIN; kb += 32) {
        __syncthreads();
        #pragma unroll
        for (int i = tid; i < 1024; i += 256) {
            int r = i >> 3, c4 = i & 7;
            float4 v = *(const float4*)&x[(r0 + r) * DIN + kb + c4 * 4];
            uint32_t h0, l0, h1, l1;
            fsplit2(v.x, v.y, h0, l0);
            fsplit2(v.z, v.w, h1, l1);
            *(uint2*)&xh[r * XSB + c4 * 4] = make_uint2(h0, h1);
            *(uint2*)&xl[r * XSB + c4 * 4] = make_uint2(l0, l1);
        }
        #pragma unroll
        for (int i = tid; i < 512; i += 256) {
            int n = i >> 3, c4 = i & 7;
            *(uint2*)&wh[n * XSB + c4 * 4] = *(const uint2*)&g_wh[p][n * DIN + kb + c4 * 4];
            *(uint2*)&wl[n * XSB + c4 * 4] = *(const uint2*)&g_wl[p][n * DIN + kb + c4 * 4];
        }
        __syncthreads();

        #pragma unroll
        for (int kc = 0; kc < 2; kc++) {
            const int ra = w * 16 + g, k0 = kc * 16 + 2 * t;
            uint32_t ah[4], al[4];
            ah[0] = *(const uint32_t*)&xh[ra * XSB + k0];
            ah[1] = *(const uint32_t*)&xh[(ra + 8) * XSB + k0];
            ah[2] = *(const uint32_t*)&xh[ra * XSB + k0 + 8];
            ah[3] = *(const uint32_t*)&xh[(ra + 8) * XSB + k0 + 8];
            al[0] = *(const uint32_t*)&xl[ra * XSB + k0];
            al[1] = *(const uint32_t*)&xl[(ra + 8) * XSB + k0];
            al[2] = *(const uint32_t*)&xl[ra * XSB + k0 + 8];
            al[3] = *(const uint32_t*)&xl[(ra + 8) * XSB + k0 + 8];
            #pragma unroll
            for (int nf = 0; nf < 8; nf++) {
                const int nr = nf * 8 + g;
                uint32_t b0 = *(const uint32_t*)&wh[nr * XSB + k0];
                uint32_t b1 = *(const uint32_t*)&wh[nr * XSB + k0 + 8];
                uint32_t d0 = *(const uint32_t*)&wl[nr * XSB + k0];
                uint32_t d1 = *(const uint32_t*)&wl[nr * XSB + k0 + 8];
                mma_f16(c[nf], ah, b0, b1);
                mma_f16acc(cc[nf], al, b0, b1);
                mma_f16acc(cc[nf], ah, d0, d1);
            }
        }
    }

    // fold f16 corrections into f32 accumulators
    #pragma unroll
    for (int nf = 0; nf < 8; nf++) {
        __half2 c01 = *(__half2*)&cc[nf][0];
        __half2 c23 = *(__half2*)&cc[nf][1];
        c[nf][0] += __half2float(c01.x);
        c[nf][1] += __half2float(c01.y);
        c[nf][2] += __half2float(c23.x);
        c[nf][3] += __half2float(c23.y);
    }

    const int rowA = r0 + w * 16 + g, rowB = rowA + 8;
    if (p == 2) {
        #pragma unroll
        for (int nf = 0; nf < 8; nf++) {
            int c0 = nf * 8 + 2 * t;
            g_vh[c0 * SEQ + rowA]       = __float2half_rn(c[nf][0]);
            g_vh[(c0 + 1) * SEQ + rowA] = __float2half_rn(c[nf][1]);
            g_vh[c0 * SEQ + rowB]       = __float2half_rn(c[nf][2]);
            g_vh[(c0 + 1) * SEQ + rowB] = __float2half_rn(c[nf][3]);
        }
    } else {
        __half* dh = (p == 0) ? g_qh : g_kh;
        __half* dl = (p == 0) ? g_ql : g_kl;
        const float sc = (p == 0) ? QK_SCALE : 1.0f;
        #pragma unroll
        for (int nf = 0; nf < 8; nf++) {
            uint32_t hA, lA, hB, lB;
            fsplit2(c[nf][0] * sc, c[nf][1] * sc, hA, lA);
            fsplit2(c[nf][2] * sc, c[nf][3] * sc, hB, lB);
            int off = nf * 8 + 2 * t;
            *(uint32_t*)&dh[rowA * D + off] = hA;
            *(uint32_t*)&dl[rowA * D + off] = lA;
            *(uint32_t*)&dh[rowB * D + off] = hB;
            *(uint32_t*)&dl[rowB * D + off] = lB;
        }
    }
}

// ---------------------------------------------------------------------------
// Kernel 2: flash attention, occ 3.  QK = fp16 2-split 3-pass f32-acc,
// PV = single-pass fp16.  Paired accumulator chains for 2x MMA ILP.
// Dynamic work-stealing, double-buffered cp.async.
// ---------------------------------------------------------------------------
__global__ __launch_bounds__(128, 3) void attn_kernel() {
    extern __shared__ __half smh[];
    __shared__ int sm_next;
    const uint32_t sbase = smem_u32(smh);

    const int tid = threadIdx.x, w = tid >> 5, lane = tid & 31;
    const int g = lane >> 2, t = lane & 3;

    const uint32_t lmo = (uint32_t)((lane & 7) * KST + (lane >> 3) * 8) * 2u;
    const uint32_t qlo_lm = sbase + (uint32_t)QLO_HALF * 2u
        + (uint32_t)((w * 16 + (lane & 15)) * KST + (lane >> 4) * 8) * 2u;

    auto issue_tile = [&](int kt, int buf) {
        #pragma unroll
        for (int i = tid; i < 1536; i += 128) {
            int arr = i >> 9, rem = i & 511, r = rem >> 3, c8 = rem & 7;
            const __half* src;
            if      (arr == 0) src = &g_kh[(kt + r) * D + c8 * 8];
            else if (arr == 1) src = &g_kl[(kt + r) * D + c8 * 8];
            else               src = &g_vh[r * SEQ + kt + c8 * 8];
            uint32_t dst = sbase + (uint32_t)buf * BUFB
                         + (uint32_t)(arr * 64 * KST + r * KST + c8 * 8) * 2u;
            cp16(dst, src);
        }
        CP_COMMIT();
    };

    if (tid == 0) sm_next = (int)atomicAdd(&g_ctr, 1u);
    __syncthreads();
    int u = sm_next;
    if (u < TOTAL_UNITS) issue_tile((u & 15) * (TILES_PER_UNIT * BN), 0);

    while (u < TOTAL_UNITS) {
        const int rb = u >> 4, sl = u & 15;
        const int k0 = sl * (TILES_PER_UNIT * BN);
        const int rowA = rb * 64 + w * 16 + g, rowB = rowA + 8;

        // stage Q-lo tile into smem
        #pragma unroll
        for (int i = tid; i < 512; i += 128) {
            int r = i >> 3, c8 = i & 7;
            *(uint4*)&smh[QLO_HALF + r * KST + c8 * 8] =
                *(const uint4*)&g_ql[(rb * 64 + r) * D + c8 * 8];
        }

        // Q-hi fragments (registers, whole unit)
        uint32_t qh[4][4];
        #pragma unroll
        for (int kc = 0; kc < 4; kc++) {
            int kk0 = kc * 16 + 2 * t;
            qh[kc][0] = *(const uint32_t*)&g_qh[rowA * D + kk0];
            qh[kc][1] = *(const uint32_t*)&g_qh[rowB * D + kk0];
            qh[kc][2] = *(const uint32_t*)&g_qh[rowA * D + kk0 + 8];
            qh[kc][3] = *(const uint32_t*)&g_qh[rowB * D + kk0 + 8];
        }

        float o[8][4];
        #pragma unroll
        for (int nf = 0; nf < 8; nf++)
            #pragma unroll
            for (int i = 0; i < 4; i++) o[nf][i] = 0.0f;
        float m_a = -INFINITY, m_b = -INFINITY, l_a = 0.0f, l_b = 0.0f;

        int next_u = TOTAL_UNITS;

        for (int tt = 0; tt < TILES_PER_UNIT; tt++) {
            bool pref = true;
            if (tt + 1 < TILES_PER_UNIT) {
                issue_tile(k0 + (tt + 1) * BN, (tt + 1) & 1);
            } else {
                if (tid == 0) sm_next = (int)atomicAdd(&g_ctr, 1u);
                __syncthreads();
                next_u = sm_next;
                if (next_u < TOTAL_UNITS)
                    issue_tile((next_u & 15) * (TILES_PER_UNIT * BN), 0);
                else pref = false;
            }
            if (pref) { CP_WAIT1(); } else { CP_WAIT0(); }
            __syncthreads();

            const uint32_t tb = sbase + (uint32_t)(tt & 1) * BUFB;
            const uint32_t akh = tb + lmo;
            const uint32_t akl = akh + (uint32_t)(64 * KST) * 2u;
            const uint32_t avh = akl + (uint32_t)(64 * KST) * 2u;

            // Q-lo A-fragments for this tile (short-lived)
            uint32_t qlf[4][4];
            #pragma unroll
            for (int kc = 0; kc < 4; kc++)
                ldm_x4(qlf[kc][0], qlf[kc][1], qlf[kc][2], qlf[kc][3],
                       qlo_lm + (uint32_t)kc * 32u);

            // ---- S = Q K^T : paired j-chains for 2x ILP ----
            float s_[8][4];
            #pragma unroll
            for (int j = 0; j < 8; j++)
                #pragma unroll
                for (int i = 0; i < 4; i++) s_[j][i] = 0.0f;
            #pragma unroll
            for (int jp = 0; jp < 4; jp++) {
                const int j0 = 2 * jp, j1 = j0 + 1;
                const uint32_t rj0 = (uint32_t)(j0 * 8 * KST) * 2u;
                const uint32_t rj1 = (uint32_t)(j1 * 8 * KST) * 2u;
                uint32_t f0[8], f1[8];
                // K-hi fragments for both rows of the pair
                ldm_x4(f0[0], f0[1], f0[2], f0[3], akh + rj0);
                ldm_x4(f0[4], f0[5], f0[6], f0[7], akh + rj0 + 64);
                ldm_x4(f1[0], f1[1], f1[2], f1[3], akh + rj1);
                ldm_x4(f1[4], f1[5], f1[6], f1[7], akh + rj1 + 64);
                #pragma unroll
                for (int kc = 0; kc < 4; kc++) {
                    mma_f16(s_[j0], qh[kc],  f0[2 * kc], f0[2 * kc + 1]);
                    mma_f16(s_[j1], qh[kc],  f1[2 * kc], f1[2 * kc + 1]);
                    mma_f16(s_[j0], qlf[kc], f0[2 * kc], f0[2 * kc + 1]);
                    mma_f16(s_[j1], qlf[kc], f1[2 * kc], f1[2 * kc + 1]);
                }
                // K-lo fragments reuse the same registers
                ldm_x4(f0[0], f0[1], f0[2], f0[3], akl + rj0);
                ldm_x4(f0[4], f0[5], f0[6], f0[7], akl + rj0 + 64);
                ldm_x4(f1[0], f1[1], f1[2], f1[3], akl + rj1);
                ldm_x4(f1[4], f1[5], f1[6], f1[7], akl + rj1 + 64);
                #pragma unroll
                for (int kc = 0; kc < 4; kc++) {
                    mma_f16(s_[j0], qh[kc], f0[2 * kc], f0[2 * kc + 1]);
                    mma_f16(s_[j1], qh[kc], f1[2 * kc], f1[2 * kc + 1]);
                }
            }

            // ---- online softmax (base-2) ----
            float mxa = -INFINITY, mxb = -INFINITY;
            #pragma unroll
            for (int j = 0; j < 8; j++) {
                mxa = fmaxf(mxa, fmaxf(s_[j][0], s_[j][1]));
                mxb = fmaxf(mxb, fmaxf(s_[j][2], s_[j][3]));
            }
            mxa = fmaxf(mxa, __shfl_xor_sync(0xffffffffu, mxa, 1));
            mxa = fmaxf(mxa, __shfl_xor_sync(0xffffffffu, mxa, 2));
            mxb = fmaxf(mxb, __shfl_xor_sync(0xffffffffu, mxb, 1));
            mxb = fmaxf(mxb, __shfl_xor_sync(0xffffffffu, mxb, 2));
            float mna = fmaxf(m_a, mxa), mnb = fmaxf(m_b, mxb);
            float ca = ex2(m_a - mna), cb = ex2(m_b - mnb);
            m_a = mna; m_b = mnb;
            float ra = 0.0f, rb2 = 0.0f;
            #pragma unroll
            for (int j = 0; j < 8; j++) {
                s_[j][0] = ex2(s_[j][0] - m_a);
                s_[j][1] = ex2(s_[j][1] - m_a);
                s_[j][2] = ex2(s_[j][2] - m_b);
                s_[j][3] = ex2(s_[j][3] - m_b);
                ra  += s_[j][0] + s_[j][1];
                rb2 += s_[j][2] + s_[j][3];
            }
            l_a = l_a * ca + ra;
            l_b = l_b * cb + rb2;
            #pragma unroll
            for (int nf = 0; nf < 8; nf++) {
                o[nf][0] *= ca; o[nf][1] *= ca;
                o[nf][2] *= cb; o[nf][3] *= cb;
            }

            // ---- pack P (fp16) ----
            uint32_t ah[4][4];
            #pragma unroll
            for (int kk = 0; kk < 4; kk++) {
                ah[kk][0] = pack_f16(s_[2 * kk][0], s_[2 * kk][1]);
                ah[kk][1] = pack_f16(s_[2 * kk][2], s_[2 * kk][3]);
                ah[kk][2] = pack_f16(s_[2 * kk + 1][0], s_[2 * kk + 1][1]);
                ah[kk][3] = pack_f16(s_[2 * kk + 1][2], s_[2 * kk + 1][3]);
            }

            // ---- O += P V : paired nf-chains for 2x ILP ----
            #pragma unroll
            for (int np = 0; np < 4; np++) {
                const int n0 = 2 * np, n1 = n0 + 1;
                const uint32_t rn0 = (uint32_t)(n0 * 8 * KST) * 2u;
                const uint32_t rn1 = (uint32_t)(n1 * 8 * KST) * 2u;
                uint32_t f0[8], f1[8];
                ldm_x4(f0[0], f0[1], f0[2], f0[3], avh + rn0);
                ldm_x4(f0[4], f0[5], f0[6], f0[7], avh + rn0 + 64);
                ldm_x4(f1[0], f1[1], f1[2], f1[3], avh + rn1);
                ldm_x4(f1[4], f1[5], f1[6], f1[7], avh + rn1 + 64);
                #pragma unroll
                for (int kk = 0; kk < 4; kk++) {
                    mma_f16(o[n0], ah[kk], f0[2 * kk], f0[2 * kk + 1]);
                    mma_f16(o[n1], ah[kk], f1[2 * kk], f1[2 * kk + 1]);
                }
            }
            __syncthreads();
        }

        // ---- unit epilogue ----
        float la = l_a + __shfl_xor_sync(0xffffffffu, l_a, 1);
        la += __shfl_xor_sync(0xffffffffu, la, 2);
        float lb = l_b + __shfl_xor_sync(0xffffffffu, l_b, 1);
        lb += __shfl_xor_sync(0xffffffffu, lb, 2);

        #pragma unroll
        for (int nf = 0; nf < 8; nf++) {
            *(float2*)&g_po[sl][rowA * D + nf * 8 + 2 * t] = make_float2(o[nf][0], o[nf][1]);
            *(float2*)&g_po[sl][rowB * D + nf * 8 + 2 * t] = make_float2(o[nf][2], o[nf][3]);
        }
        if (t == 0) {
            g_pm[sl][rowA] = m_a; g_pl[sl][rowA] = la;
            g_pm[sl][rowB] = m_b; g_pl[sl][rowB] = lb;
        }
        u = next_u;
    }
}

// ---------------------------------------------------------------------------
// Kernel 3: combine the 16 KV slices, float4-vectorized.
// ---------------------------------------------------------------------------
__global__ __launch_bounds__(256) void combine_kernel(float* __restrict__ out) {
    __shared__ float ws[16][NSPLIT];
    const int tid = threadIdx.x;
    const int r0 = blockIdx.x * 16;

    if (tid < 16) {
        int r = r0 + tid;
        float M = -INFINITY;
        #pragma unroll
        for (int i = 0; i < NSPLIT; i++) M = fmaxf(M, g_pm[i][r]);
        float wv[NSPLIT];
        float den = 0.0f;
        #pragma unroll
        for (int i = 0; i < NSPLIT; i++) {
            wv[i] = ex2(g_pm[i][r] - M);
            den += g_pl[i][r] * wv[i];
        }
        float inv = __frcp_rn(den);
        #pragma unroll
        for (int i = 0; i < NSPLIT; i++) ws[tid][i] = wv[i] * inv;
    }
    __syncthreads();

    const int idx4 = (blockIdx.x * 256 + tid) * 4;
    const int rloc = (idx4 >> 6) & 15;
    float4 acc = make_float4(0.f, 0.f, 0.f, 0.f);
    #pragma unroll
    for (int i = 0; i < NSPLIT; i++) {
        float4 v = *(const float4*)&g_po[i][idx4];
        float wgt = ws[rloc][i];
        acc.x += v.x * wgt; acc.y += v.y * wgt;
        acc.z += v.z * wgt; acc.w += v.w * wgt;
    }
    *(float4*)&out[idx4] = acc;
}

// ---------------------------------------------------------------------------
extern "C" void kernel_launch(void* const* d_in, const int* in_sizes, int n_in,
                              void* d_out, int out_size) {
    const float* x  = (const float*)d_in[0];
    const float* Wq = (const float*)d_in[1];
    const float* Wk = (const float*)d_in[2];
    const float* Wv = (const float*)d_in[3];
    float* out = (float*)d_out;

    cudaFuncSetAttribute(qkv_kernel,
                         cudaFuncAttributeMaxDynamicSharedMemorySize, QKV_SMEM);
    cudaFuncSetAttribute(attn_kernel,
                         cudaFuncAttributeMaxDynamicSharedMemorySize, ATT_SMEM);

    zero_ctr_kernel<<<1, 1>>>();
    prep_kernel<<<(3 * D * DIN) / 256, 256>>>(Wq, Wk, Wv);
    qkv_kernel<<<dim3(SEQ / 128, 3), 256, QKV_SMEM>>>(x);
    attn_kernel<<<GRID_ATTN, 128, ATT_SMEM>>>();
    combine_kernel<<<(SEQ * D) / 1024, 256>>>(out);
}

// round 14
// speedup vs baseline: 1.1083x; 1.1083x over previous
#include <cuda_runtime.h>
#include <cuda_fp16.h>
#include <cstdint>
#include <math.h>

#define SEQ 8192
#define DIN 512
#define D   64
#define BN  64
#define NSPLIT 16
#define TILES_PER_UNIT 8            // 8 * 64 = 512 keys per unit
#define TOTAL_UNITS (64 * NSPLIT)   // 1024 (128 rows per unit)
#define GRID_ATTN 304               // 2 CTAs x 152 SMs
#define QK_SCALE 0.18033688011112042f   // 0.125 * log2(e)
#define XSB 40      // qkv smem row stride (halves)
#define KST 72      // attn smem row stride (halves)
#define BUFB (3 * 64 * KST * 2)     // one attn buffer: 27648 B (kh, kl, vh)
#define QLO_HALF (BUFB)             // Q-lo tile offset in halves (2*BUFB bytes)
#define ATT_SMEM (2 * BUFB + 128 * KST * 2)   // 73728 B

// ---------------- device scratch (no cudaMalloc allowed) ----------------
__device__ __half g_wh[3][D * DIN], g_wl[3][D * DIN];   // W^T fp16 hi/lo
__device__ __half g_qh[SEQ * D], g_ql[SEQ * D];         // Q fp16 hi/lo (scaled)
__device__ __half g_kh[SEQ * D], g_kl[SEQ * D];         // K fp16 hi/lo
__device__ __half g_vh[D * SEQ];                        // V^T fp16 (single)
__device__ float g_po[NSPLIT][SEQ * D];
__device__ float g_pm[NSPLIT][SEQ];
__device__ float g_pl[NSPLIT][SEQ];
__device__ unsigned int g_ctr;                          // dynamic unit counter

// ---------------- helpers ----------------
__device__ __forceinline__ float ex2(float x) {
    float r; asm("ex2.approx.f32 %0, %1;" : "=f"(r) : "f"(x)); return r;
}
__device__ __forceinline__ void mma_f16(float* c, const uint32_t* a,
                                        uint32_t b0, uint32_t b1) {
    asm volatile(
        "mma.sync.aligned.m16n8k16.row.col.f32.f16.f16.f32 "
        "{%0,%1,%2,%3},{%4,%5,%6,%7},{%8,%9},{%0,%1,%2,%3};"
        : "+f"(c[0]), "+f"(c[1]), "+f"(c[2]), "+f"(c[3])
        : "r"(a[0]), "r"(a[1]), "r"(a[2]), "r"(a[3]), "r"(b0), "r"(b1));
}
__device__ __forceinline__ void mma_f16acc(uint32_t* c, const uint32_t* a,
                                           uint32_t b0, uint32_t b1) {
    asm volatile(
        "mma.sync.aligned.m16n8k16.row.col.f16.f16.f16.f16 "
        "{%0,%1},{%2,%3,%4,%5},{%6,%7},{%0,%1};"
        : "+r"(c[0]), "+r"(c[1])
        : "r"(a[0]), "r"(a[1]), "r"(a[2]), "r"(a[3]), "r"(b0), "r"(b1));
}
__device__ __forceinline__ void ldm_x4(uint32_t& r0, uint32_t& r1,
                                       uint32_t& r2, uint32_t& r3, uint32_t addr) {
    asm volatile("ldmatrix.sync.aligned.m8n8.x4.shared.b16 {%0,%1,%2,%3}, [%4];"
                 : "=r"(r0), "=r"(r1), "=r"(r2), "=r"(r3) : "r"(addr));
}
__device__ __forceinline__ uint32_t pack_f16(float lo, float hi) {
    uint32_t r;
    asm("cvt.rn.f16x2.f32 %0, %1, %2;" : "=r"(r) : "f"(hi), "f"(lo));
    return r;
}
__device__ __forceinline__ void fsplit2(float v0, float v1, uint32_t& h, uint32_t& l) {
    __half h0 = __float2half_rn(v0), h1 = __float2half_rn(v1);
    float l0 = v0 - __half2float(h0), l1 = v1 - __half2float(h1);
    __half2 hh(h0, h1);
    __half2 ll(__float2half_rn(l0), __float2half_rn(l1));
    h = *(uint32_t*)&hh;
    l = *(uint32_t*)&ll;
}
__device__ __forceinline__ uint32_t smem_u32(const void* p) {
    uint32_t a;
    asm("{ .reg .u64 t; cvta.to.shared.u64 t, %1; cvt.u32.u64 %0, t; }" : "=r"(a) : "l"(p));
    return a;
}
__device__ __forceinline__ void cp16(uint32_t dst, const void* src) {
    asm volatile("cp.async.cg.shared.global [%0], [%1], 16;" :: "r"(dst), "l"(src) : "memory");
}
#define CP_COMMIT() asm volatile("cp.async.commit_group;" ::: "memory")
#define CP_WAIT0()  asm volatile("cp.async.wait_group 0;" ::: "memory")
#define CP_WAIT1()  asm volatile("cp.async.wait_group 1;" ::: "memory")

// ---------------------------------------------------------------------------
__global__ void zero_ctr_kernel() { g_ctr = 0u; }

// ---------------------------------------------------------------------------
// Kernel 0: split W^T into fp16 hi/lo.
// ---------------------------------------------------------------------------
__global__ void prep_kernel(const float* __restrict__ Wq,
                            const float* __restrict__ Wk,
                            const float* __restrict__ Wv) {
    int i = blockIdx.x * 256 + threadIdx.x;
    int p = i / (D * DIN), r = i % (D * DIN);
    int n = r / DIN, k = r % DIN;
    const float* W = (p == 0) ? Wq : (p == 1) ? Wk : Wv;
    float w = W[k * D + n];
    __half h = __float2half_rn(w);
    g_wh[p][n * DIN + k] = h;
    g_wl[p][n * DIN + k] = __float2half_rn(w - __half2float(h));
}

// ---------------------------------------------------------------------------
// Kernel 1: QKV projection (unchanged from round 12).
// ---------------------------------------------------------------------------
#define QKV_SMEM ((128 * XSB * 2 + 64 * XSB * 2) * 2)   // 30720 B

__global__ __launch_bounds__(256, 2) void qkv_kernel(const float* __restrict__ x) {
    extern __shared__ __half qsm[];
    __half* xh = qsm;
    __half* xl = xh + 128 * XSB;
    __half* wh = xl + 128 * XSB;
    __half* wl = wh + 64 * XSB;

    const int tid = threadIdx.x, w = tid >> 5, lane = tid & 31;
    const int g = lane >> 2, t = lane & 3;
    const int r0 = blockIdx.x * 128;
    const int p = blockIdx.y;

    float c[8][4];
    uint32_t cc[8][2];
    #pragma unroll
    for (int nf = 0; nf < 8; nf++) {
        cc[nf][0] = 0u; cc[nf][1] = 0u;
        #pragma unroll
        for (int i = 0; i < 4; i++) c[nf][i] = 0.0f;
    }

    for (int kb = 0; kb < DIN; kb += 32) {
        __syncthreads();
        #pragma unroll
        for (int i = tid; i < 1024; i += 256) {
            int r = i >> 3, c4 = i & 7;
            float4 v = *(const float4*)&x[(r0 + r) * DIN + kb + c4 * 4];
            uint32_t h0, l0, h1, l1;
            fsplit2(v.x, v.y, h0, l0);
            fsplit2(v.z, v.w, h1, l1);
            *(uint2*)&xh[r * XSB + c4 * 4] = make_uint2(h0, h1);
            *(uint2*)&xl[r * XSB + c4 * 4] = make_uint2(l0, l1);
        }
        #pragma unroll
        for (int i = tid; i < 512; i += 256) {
            int n = i >> 3, c4 = i & 7;
            *(uint2*)&wh[n * XSB + c4 * 4] = *(const uint2*)&g_wh[p][n * DIN + kb + c4 * 4];
            *(uint2*)&wl[n * XSB + c4 * 4] = *(const uint2*)&g_wl[p][n * DIN + kb + c4 * 4];
        }
        __syncthreads();

        #pragma unroll
        for (int kc = 0; kc < 2; kc++) {
            const int ra = w * 16 + g, k0 = kc * 16 + 2 * t;
            uint32_t ah[4], al[4];
            ah[0] = *(const uint32_t*)&xh[ra * XSB + k0];
            ah[1] = *(const uint32_t*)&xh[(ra + 8) * XSB + k0];
            ah[2] = *(const uint32_t*)&xh[ra * XSB + k0 + 8];
            ah[3] = *(const uint32_t*)&xh[(ra + 8) * XSB + k0 + 8];
            al[0] = *(const uint32_t*)&xl[ra * XSB + k0];
            al[1] = *(const uint32_t*)&xl[(ra + 8) * XSB + k0];
            al[2] = *(const uint32_t*)&xl[ra * XSB + k0 + 8];
            al[3] = *(const uint32_t*)&xl[(ra + 8) * XSB + k0 + 8];
            #pragma unroll
            for (int nf = 0; nf < 8; nf++) {
                const int nr = nf * 8 + g;
                uint32_t b0 = *(const uint32_t*)&wh[nr * XSB + k0];
                uint32_t b1 = *(const uint32_t*)&wh[nr * XSB + k0 + 8];
                uint32_t d0 = *(const uint32_t*)&wl[nr * XSB + k0];
                uint32_t d1 = *(const uint32_t*)&wl[nr * XSB + k0 + 8];
                mma_f16(c[nf], ah, b0, b1);
                mma_f16acc(cc[nf], al, b0, b1);
                mma_f16acc(cc[nf], ah, d0, d1);
            }
        }
    }

    #pragma unroll
    for (int nf = 0; nf < 8; nf++) {
        __half2 c01 = *(__half2*)&cc[nf][0];
        __half2 c23 = *(__half2*)&cc[nf][1];
        c[nf][0] += __half2float(c01.x);
        c[nf][1] += __half2float(c01.y);
        c[nf][2] += __half2float(c23.x);
        c[nf][3] += __half2float(c23.y);
    }

    const int rowA = r0 + w * 16 + g, rowB = rowA + 8;
    if (p == 2) {
        #pragma unroll
        for (int nf = 0; nf < 8; nf++) {
            int c0 = nf * 8 + 2 * t;
            g_vh[c0 * SEQ + rowA]       = __float2half_rn(c[nf][0]);
            g_vh[(c0 + 1) * SEQ + rowA] = __float2half_rn(c[nf][1]);
            g_vh[c0 * SEQ + rowB]       = __float2half_rn(c[nf][2]);
            g_vh[(c0 + 1) * SEQ + rowB] = __float2half_rn(c[nf][3]);
        }
    } else {
        __half* dh = (p == 0) ? g_qh : g_kh;
        __half* dl = (p == 0) ? g_ql : g_kl;
        const float sc = (p == 0) ? QK_SCALE : 1.0f;
        #pragma unroll
        for (int nf = 0; nf < 8; nf++) {
            uint32_t hA, lA, hB, lB;
            fsplit2(c[nf][0] * sc, c[nf][1] * sc, hA, lA);
            fsplit2(c[nf][2] * sc, c[nf][3] * sc, hB, lB);
            int off = nf * 8 + 2 * t;
            *(uint32_t*)&dh[rowA * D + off] = hA;
            *(uint32_t*)&dl[rowA * D + off] = lA;
            *(uint32_t*)&dh[rowB * D + off] = hB;
            *(uint32_t*)&dl[rowB * D + off] = lB;
        }
    }
}

// ---------------------------------------------------------------------------
// Kernel 2: flash attention, M=32 per warp (two m16 subtiles share all
// K/V fragment loads -> bytes/HMMA halved).  BM=128 rows per unit.
// ---------------------------------------------------------------------------
__global__ __launch_bounds__(128, 2) void attn_kernel() {
    extern __shared__ __half smh[];
    __shared__ int sm_next;
    const uint32_t sbase = smem_u32(smh);

    const int tid = threadIdx.x, w = tid >> 5, lane = tid & 31;
    const int g = lane >> 2, t = lane & 3;

    const uint32_t lmo = (uint32_t)((lane & 7) * KST + (lane >> 3) * 8) * 2u;
    // Q-lo A-fragment ldmatrix addresses for the two m-subtiles
    uint32_t qlo_lm[2];
    #pragma unroll
    for (int ms = 0; ms < 2; ms++)
        qlo_lm[ms] = sbase + (uint32_t)QLO_HALF * 2u
            + (uint32_t)((w * 32 + ms * 16 + (lane & 15)) * KST + (lane >> 4) * 8) * 2u;

    auto issue_tile = [&](int kt, int buf) {
        #pragma unroll
        for (int i = tid; i < 1536; i += 128) {
            int arr = i >> 9, rem = i & 511, r = rem >> 3, c8 = rem & 7;
            const __half* src;
            if      (arr == 0) src = &g_kh[(kt + r) * D + c8 * 8];
            else if (arr == 1) src = &g_kl[(kt + r) * D + c8 * 8];
            else               src = &g_vh[r * SEQ + kt + c8 * 8];
            uint32_t dst = sbase + (uint32_t)buf * BUFB
                         + (uint32_t)(arr * 64 * KST + r * KST + c8 * 8) * 2u;
            cp16(dst, src);
        }
        CP_COMMIT();
    };

    if (tid == 0) sm_next = (int)atomicAdd(&g_ctr, 1u);
    __syncthreads();
    int u = sm_next;
    if (u < TOTAL_UNITS) issue_tile((u & 15) * (TILES_PER_UNIT * BN), 0);

    while (u < TOTAL_UNITS) {
        const int rb = u >> 4, sl = u & 15;
        const int k0 = sl * (TILES_PER_UNIT * BN);

        // stage Q-lo tile (128 rows) into smem
        #pragma unroll
        for (int i = tid; i < 1024; i += 128) {
            int r = i >> 3, c8 = i & 7;
            *(uint4*)&smh[QLO_HALF + r * KST + c8 * 8] =
                *(const uint4*)&g_ql[(rb * 128 + r) * D + c8 * 8];
        }

        // Q-hi fragments for both m-subtiles (persistent)
        uint32_t qh[2][4][4];
        #pragma unroll
        for (int ms = 0; ms < 2; ms++) {
            const int rA = rb * 128 + w * 32 + ms * 16 + g, rB = rA + 8;
            #pragma unroll
            for (int kc = 0; kc < 4; kc++) {
                int kk0 = kc * 16 + 2 * t;
                qh[ms][kc][0] = *(const uint32_t*)&g_qh[rA * D + kk0];
                qh[ms][kc][1] = *(const uint32_t*)&g_qh[rB * D + kk0];
                qh[ms][kc][2] = *(const uint32_t*)&g_qh[rA * D + kk0 + 8];
                qh[ms][kc][3] = *(const uint32_t*)&g_qh[rB * D + kk0 + 8];
            }
        }

        float o[2][8][4];
        float m_a[2], m_b[2], l_a[2], l_b[2];
        #pragma unroll
        for (int ms = 0; ms < 2; ms++) {
            m_a[ms] = -INFINITY; m_b[ms] = -INFINITY;
            l_a[ms] = 0.0f; l_b[ms] = 0.0f;
            #pragma unroll
            for (int nf = 0; nf < 8; nf++)
                #pragma unroll
                for (int i = 0; i < 4; i++) o[ms][nf][i] = 0.0f;
        }

        int next_u = TOTAL_UNITS;

        for (int tt = 0; tt < TILES_PER_UNIT; tt++) {
            bool pref = true;
            if (tt + 1 < TILES_PER_UNIT) {
                issue_tile(k0 + (tt + 1) * BN, (tt + 1) & 1);
            } else {
                if (tid == 0) sm_next = (int)atomicAdd(&g_ctr, 1u);
                __syncthreads();
                next_u = sm_next;
                if (next_u < TOTAL_UNITS)
                    issue_tile((next_u & 15) * (TILES_PER_UNIT * BN), 0);
                else pref = false;
            }
            if (pref) { CP_WAIT1(); } else { CP_WAIT0(); }
            __syncthreads();

            const uint32_t tb = sbase + (uint32_t)(tt & 1) * BUFB;
            const uint32_t akh = tb + lmo;
            const uint32_t akl = akh + (uint32_t)(64 * KST) * 2u;
            const uint32_t avh = akl + (uint32_t)(64 * KST) * 2u;

            // Q-lo A-fragments for both m-subtiles (transient this tile)
            uint32_t qlf[2][4][4];
            #pragma unroll
            for (int ms = 0; ms < 2; ms++)
                #pragma unroll
                for (int kc = 0; kc < 4; kc++)
                    ldm_x4(qlf[ms][kc][0], qlf[ms][kc][1], qlf[ms][kc][2], qlf[ms][kc][3],
                           qlo_lm[ms] + (uint32_t)kc * 32u);

            // ---- S = Q K^T : K fragments shared by both m-subtiles ----
            float s_[2][8][4];
            #pragma unroll
            for (int j = 0; j < 8; j++) {
                const uint32_t rj = (uint32_t)(j * 8 * KST) * 2u;
                uint32_t f[8];
                ldm_x4(f[0], f[1], f[2], f[3], akh + rj);
                ldm_x4(f[4], f[5], f[6], f[7], akh + rj + 64);
                #pragma unroll
                for (int ms = 0; ms < 2; ms++)
                    #pragma unroll
                    for (int i = 0; i < 4; i++) s_[ms][j][i] = 0.0f;
                #pragma unroll
                for (int kc = 0; kc < 4; kc++) {
                    mma_f16(s_[0][j], qh[0][kc],  f[2 * kc], f[2 * kc + 1]);
                    mma_f16(s_[1][j], qh[1][kc],  f[2 * kc], f[2 * kc + 1]);
                    mma_f16(s_[0][j], qlf[0][kc], f[2 * kc], f[2 * kc + 1]);
                    mma_f16(s_[1][j], qlf[1][kc], f[2 * kc], f[2 * kc + 1]);
                }
                ldm_x4(f[0], f[1], f[2], f[3], akl + rj);
                ldm_x4(f[4], f[5], f[6], f[7], akl + rj + 64);
                #pragma unroll
                for (int kc = 0; kc < 4; kc++) {
                    mma_f16(s_[0][j], qh[0][kc], f[2 * kc], f[2 * kc + 1]);
                    mma_f16(s_[1][j], qh[1][kc], f[2 * kc], f[2 * kc + 1]);
                }
            }

            // ---- online softmax (base-2) + pack P, per m-subtile ----
            uint32_t ah[2][4][4];
            #pragma unroll
            for (int ms = 0; ms < 2; ms++) {
                float mxa = -INFINITY, mxb = -INFINITY;
                #pragma unroll
                for (int j = 0; j < 8; j++) {
                    mxa = fmaxf(mxa, fmaxf(s_[ms][j][0], s_[ms][j][1]));
                    mxb = fmaxf(mxb, fmaxf(s_[ms][j][2], s_[ms][j][3]));
                }
                mxa = fmaxf(mxa, __shfl_xor_sync(0xffffffffu, mxa, 1));
                mxa = fmaxf(mxa, __shfl_xor_sync(0xffffffffu, mxa, 2));
                mxb = fmaxf(mxb, __shfl_xor_sync(0xffffffffu, mxb, 1));
                mxb = fmaxf(mxb, __shfl_xor_sync(0xffffffffu, mxb, 2));
                float mna = fmaxf(m_a[ms], mxa), mnb = fmaxf(m_b[ms], mxb);
                float ca = ex2(m_a[ms] - mna), cb = ex2(m_b[ms] - mnb);
                m_a[ms] = mna; m_b[ms] = mnb;
                float ra = 0.0f, rb2 = 0.0f;
                #pragma unroll
                for (int j = 0; j < 8; j++) {
                    s_[ms][j][0] = ex2(s_[ms][j][0] - mna);
                    s_[ms][j][1] = ex2(s_[ms][j][1] - mna);
                    s_[ms][j][2] = ex2(s_[ms][j][2] - mnb);
                    s_[ms][j][3] = ex2(s_[ms][j][3] - mnb);
                    ra  += s_[ms][j][0] + s_[ms][j][1];
                    rb2 += s_[ms][j][2] + s_[ms][j][3];
                }
                l_a[ms] = l_a[ms] * ca + ra;
                l_b[ms] = l_b[ms] * cb + rb2;
                #pragma unroll
                for (int nf = 0; nf < 8; nf++) {
                    o[ms][nf][0] *= ca; o[ms][nf][1] *= ca;
                    o[ms][nf][2] *= cb; o[ms][nf][3] *= cb;
                }
                #pragma unroll
                for (int kk = 0; kk < 4; kk++) {
                    ah[ms][kk][0] = pack_f16(s_[ms][2 * kk][0], s_[ms][2 * kk][1]);
                    ah[ms][kk][1] = pack_f16(s_[ms][2 * kk][2], s_[ms][2 * kk][3]);
                    ah[ms][kk][2] = pack_f16(s_[ms][2 * kk + 1][0], s_[ms][2 * kk + 1][1]);
                    ah[ms][kk][3] = pack_f16(s_[ms][2 * kk + 1][2], s_[ms][2 * kk + 1][3]);
                }
            }

            // ---- O += P V : V fragments shared by both m-subtiles ----
            #pragma unroll
            for (int nf = 0; nf < 8; nf++) {
                const uint32_t rn = (uint32_t)(nf * 8 * KST) * 2u;
                uint32_t f[8];
                ldm_x4(f[0], f[1], f[2], f[3], avh + rn);
                ldm_x4(f[4], f[5], f[6], f[7], avh + rn + 64);
                #pragma unroll
                for (int kk = 0; kk < 4; kk++) {
                    mma_f16(o[0][nf], ah[0][kk], f[2 * kk], f[2 * kk + 1]);
                    mma_f16(o[1][nf], ah[1][kk], f[2 * kk], f[2 * kk + 1]);
                }
            }
            __syncthreads();
        }

        // ---- unit epilogue (per m-subtile) ----
        #pragma unroll
        for (int ms = 0; ms < 2; ms++) {
            float la = l_a[ms] + __shfl_xor_sync(0xffffffffu, l_a[ms], 1);
            la += __shfl_xor_sync(0xffffffffu, la, 2);
            float lb = l_b[ms] + __shfl_xor_sync(0xffffffffu, l_b[ms], 1);
            lb += __shfl_xor_sync(0xffffffffu, lb, 2);

            const int rowA = rb * 128 + w * 32 + ms * 16 + g, rowB = rowA + 8;
            #pragma unroll
            for (int nf = 0; nf < 8; nf++) {
                *(float2*)&g_po[sl][rowA * D + nf * 8 + 2 * t] =
                    make_float2(o[ms][nf][0], o[ms][nf][1]);
                *(float2*)&g_po[sl][rowB * D + nf * 8 + 2 * t] =
                    make_float2(o[ms][nf][2], o[ms][nf][3]);
            }
            if (t == 0) {
                g_pm[sl][rowA] = m_a[ms]; g_pl[sl][rowA] = la;
                g_pm[sl][rowB] = m_b[ms]; g_pl[sl][rowB] = lb;
            }
        }
        u = next_u;
    }
}

// ---------------------------------------------------------------------------
// Kernel 3: combine the 16 KV slices, float4-vectorized.
// ---------------------------------------------------------------------------
__global__ __launch_bounds__(256) void combine_kernel(float* __restrict__ out) {
    __shared__ float ws[16][NSPLIT];
    const int tid = threadIdx.x;
    const int r0 = blockIdx.x * 16;

    if (tid < 16) {
        int r = r0 + tid;
        float M = -INFINITY;
        #pragma unroll
        for (int i = 0; i < NSPLIT; i++) M = fmaxf(M, g_pm[i][r]);
        float wv[NSPLIT];
        float den = 0.0f;
        #pragma unroll
        for (int i = 0; i < NSPLIT; i++) {
            wv[i] = ex2(g_pm[i][r] - M);
            den += g_pl[i][r] * wv[i];
        }
        float inv = __frcp_rn(den);
        #pragma unroll
        for (int i = 0; i < NSPLIT; i++) ws[tid][i] = wv[i] * inv;
    }
    __syncthreads();

    const int idx4 = (blockIdx.x * 256 + tid) * 4;
    const int rloc = (idx4 >> 6) & 15;
    float4 acc = make_float4(0.f, 0.f, 0.f, 0.f);
    #pragma unroll
    for (int i = 0; i < NSPLIT; i++) {
        float4 v = *(const float4*)&g_po[i][idx4];
        float wgt = ws[rloc][i];
        acc.x += v.x * wgt; acc.y += v.y * wgt;
        acc.z += v.z * wgt; acc.w += v.w * wgt;
    }
    *(float4*)&out[idx4] = acc;
}

// ---------------------------------------------------------------------------
extern "C" void kernel_launch(void* const* d_in, const int* in_sizes, int n_in,
                              void* d_out, int out_size) {
    const float* x  = (const float*)d_in[0];
    const float* Wq = (const float*)d_in[1];
    const float* Wk = (const float*)d_in[2];
    const float* Wv = (const float*)d_in[3];
    float* out = (float*)d_out;

    cudaFuncSetAttribute(qkv_kernel,
                         cudaFuncAttributeMaxDynamicSharedMemorySize, QKV_SMEM);
    cudaFuncSetAttribute(attn_kernel,
                         cudaFuncAttributeMaxDynamicSharedMemorySize, ATT_SMEM);

    zero_ctr_kernel<<<1, 1>>>();
    prep_kernel<<<(3 * D * DIN) / 256, 256>>>(Wq, Wk, Wv);
    qkv_kernel<<<dim3(SEQ / 128, 3), 256, QKV_SMEM>>>(x);
    attn_kernel<<<GRID_ATTN, 128, ATT_SMEM>>>();
    combine_kernel<<<(SEQ * D) / 1024, 256>>>(out);
}

// round 15
// speedup vs baseline: 1.1096x; 1.0012x over previous
#include <cuda_runtime.h>
#include <cuda_fp16.h>
#include <cstdint>
#include <math.h>

#define SEQ 8192
#define DIN 512
#define D   64
#define BN  64
#define NSPLIT 16
#define TILES_PER_UNIT 8            // 8 * 64 = 512 keys per unit
#define TOTAL_UNITS (64 * NSPLIT)   // 1024 (128 rows per unit)
#define GRID_ATTN 304               // 2 CTAs x 152 SMs
#define QK_SCALE 0.18033688011112042f   // 0.125 * log2(e)
#define XSB 40      // qkv smem row stride (halves)
#define KST 72      // attn smem row stride (halves)
#define BUFB (3 * 64 * KST * 2)     // one attn buffer: 27648 B (kh, kl, vh)
#define QLO_HALF (BUFB)             // Q-lo tile offset in halves (2*BUFB bytes)
#define ATT_SMEM (2 * BUFB + 128 * KST * 2)   // 73728 B

// ---------------- device scratch (no cudaMalloc allowed) ----------------
__device__ __half g_wh[3][D * DIN], g_wl[3][D * DIN];   // W^T fp16 hi/lo
__device__ __half g_qh[SEQ * D], g_ql[SEQ * D];         // Q fp16 hi/lo (scaled)
__device__ __half g_kh[SEQ * D], g_kl[SEQ * D];         // K fp16 hi/lo
__device__ __half g_vh[D * SEQ];                        // V^T fp16 (single)
__device__ float g_po[NSPLIT][SEQ * D];
__device__ float g_pm[NSPLIT][SEQ];
__device__ float g_pl[NSPLIT][SEQ];
__device__ unsigned int g_ctr;                          // dynamic unit counter

// ---------------- helpers ----------------
__device__ __forceinline__ float ex2(float x) {
    float r; asm("ex2.approx.f32 %0, %1;" : "=f"(r) : "f"(x)); return r;
}
__device__ __forceinline__ void mma_f16(float* c, const uint32_t* a,
                                        uint32_t b0, uint32_t b1) {
    asm volatile(
        "mma.sync.aligned.m16n8k16.row.col.f32.f16.f16.f32 "
        "{%0,%1,%2,%3},{%4,%5,%6,%7},{%8,%9},{%0,%1,%2,%3};"
        : "+f"(c[0]), "+f"(c[1]), "+f"(c[2]), "+f"(c[3])
        : "r"(a[0]), "r"(a[1]), "r"(a[2]), "r"(a[3]), "r"(b0), "r"(b1));
}
__device__ __forceinline__ void mma_f16acc(uint32_t* c, const uint32_t* a,
                                           uint32_t b0, uint32_t b1) {
    asm volatile(
        "mma.sync.aligned.m16n8k16.row.col.f16.f16.f16.f16 "
        "{%0,%1},{%2,%3,%4,%5},{%6,%7},{%0,%1};"
        : "+r"(c[0]), "+r"(c[1])
        : "r"(a[0]), "r"(a[1]), "r"(a[2]), "r"(a[3]), "r"(b0), "r"(b1));
}
__device__ __forceinline__ void ldm_x4(uint32_t& r0, uint32_t& r1,
                                       uint32_t& r2, uint32_t& r3, uint32_t addr) {
    asm volatile("ldmatrix.sync.aligned.m8n8.x4.shared.b16 {%0,%1,%2,%3}, [%4];"
                 : "=r"(r0), "=r"(r1), "=r"(r2), "=r"(r3) : "r"(addr));
}
__device__ __forceinline__ uint32_t pack_f16(float lo, float hi) {
    uint32_t r;
    asm("cvt.rn.f16x2.f32 %0, %1, %2;" : "=r"(r) : "f"(hi), "f"(lo));
    return r;
}
__device__ __forceinline__ void fsplit2(float v0, float v1, uint32_t& h, uint32_t& l) {
    __half h0 = __float2half_rn(v0), h1 = __float2half_rn(v1);
    float l0 = v0 - __half2float(h0), l1 = v1 - __half2float(h1);
    __half2 hh(h0, h1);
    __half2 ll(__float2half_rn(l0), __float2half_rn(l1));
    h = *(uint32_t*)&hh;
    l = *(uint32_t*)&ll;
}
__device__ __forceinline__ uint32_t smem_u32(const void* p) {
    uint32_t a;
    asm("{ .reg .u64 t; cvta.to.shared.u64 t, %1; cvt.u32.u64 %0, t; }" : "=r"(a) : "l"(p));
    return a;
}
__device__ __forceinline__ void cp16(uint32_t dst, const void* src) {
    asm volatile("cp.async.cg.shared.global [%0], [%1], 16;" :: "r"(dst), "l"(src) : "memory");
}
#define CP_COMMIT() asm volatile("cp.async.commit_group;" ::: "memory")
#define CP_WAIT0()  asm volatile("cp.async.wait_group 0;" ::: "memory")
#define CP_WAIT1()  asm volatile("cp.async.wait_group 1;" ::: "memory")

// ---------------------------------------------------------------------------
__global__ void zero_ctr_kernel() { g_ctr = 0u; }

// ---------------------------------------------------------------------------
// Kernel 0: split W^T into fp16 hi/lo.
// ---------------------------------------------------------------------------
__global__ void prep_kernel(const float* __restrict__ Wq,
                            const float* __restrict__ Wk,
                            const float* __restrict__ Wv) {
    int i = blockIdx.x * 256 + threadIdx.x;
    int p = i / (D * DIN), r = i % (D * DIN);
    int n = r / DIN, k = r % DIN;
    const float* W = (p == 0) ? Wq : (p == 1) ? Wk : Wv;
    float w = W[k * D + n];
    __half h = __float2half_rn(w);
    g_wh[p][n * DIN + k] = h;
    g_wl[p][n * DIN + k] = __float2half_rn(w - __half2float(h));
}

// ---------------------------------------------------------------------------
// Kernel 1: QKV projection (unchanged).
// ---------------------------------------------------------------------------
#define QKV_SMEM ((128 * XSB * 2 + 64 * XSB * 2) * 2)   // 30720 B

__global__ __launch_bounds__(256, 2) void qkv_kernel(const float* __restrict__ x) {
    extern __shared__ __half qsm[];
    __half* xh = qsm;
    __half* xl = xh + 128 * XSB;
    __half* wh = xl + 128 * XSB;
    __half* wl = wh + 64 * XSB;

    const int tid = threadIdx.x, w = tid >> 5, lane = tid & 31;
    const int g = lane >> 2, t = lane & 3;
    const int r0 = blockIdx.x * 128;
    const int p = blockIdx.y;

    float c[8][4];
    uint32_t cc[8][2];
    #pragma unroll
    for (int nf = 0; nf < 8; nf++) {
        cc[nf][0] = 0u; cc[nf][1] = 0u;
        #pragma unroll
        for (int i = 0; i < 4; i++) c[nf][i] = 0.0f;
    }

    for (int kb = 0; kb < DIN; kb += 32) {
        __syncthreads();
        #pragma unroll
        for (int i = tid; i < 1024; i += 256) {
            int r = i >> 3, c4 = i & 7;
            float4 v = *(const float4*)&x[(r0 + r) * DIN + kb + c4 * 4];
            uint32_t h0, l0, h1, l1;
            fsplit2(v.x, v.y, h0, l0);
            fsplit2(v.z, v.w, h1, l1);
            *(uint2*)&xh[r * XSB + c4 * 4] = make_uint2(h0, h1);
            *(uint2*)&xl[r * XSB + c4 * 4] = make_uint2(l0, l1);
        }
        #pragma unroll
        for (int i = tid; i < 512; i += 256) {
            int n = i >> 3, c4 = i & 7;
            *(uint2*)&wh[n * XSB + c4 * 4] = *(const uint2*)&g_wh[p][n * DIN + kb + c4 * 4];
            *(uint2*)&wl[n * XSB + c4 * 4] = *(const uint2*)&g_wl[p][n * DIN + kb + c4 * 4];
        }
        __syncthreads();

        #pragma unroll
        for (int kc = 0; kc < 2; kc++) {
            const int ra = w * 16 + g, k0 = kc * 16 + 2 * t;
            uint32_t ah[4], al[4];
            ah[0] = *(const uint32_t*)&xh[ra * XSB + k0];
            ah[1] = *(const uint32_t*)&xh[(ra + 8) * XSB + k0];
            ah[2] = *(const uint32_t*)&xh[ra * XSB + k0 + 8];
            ah[3] = *(const uint32_t*)&xh[(ra + 8) * XSB + k0 + 8];
            al[0] = *(const uint32_t*)&xl[ra * XSB + k0];
            al[1] = *(const uint32_t*)&xl[(ra + 8) * XSB + k0];
            al[2] = *(const uint32_t*)&xl[ra * XSB + k0 + 8];
            al[3] = *(const uint32_t*)&xl[(ra + 8) * XSB + k0 + 8];
            #pragma unroll
            for (int nf = 0; nf < 8; nf++) {
                const int nr = nf * 8 + g;
                uint32_t b0 = *(const uint32_t*)&wh[nr * XSB + k0];
                uint32_t b1 = *(const uint32_t*)&wh[nr * XSB + k0 + 8];
                uint32_t d0 = *(const uint32_t*)&wl[nr * XSB + k0];
                uint32_t d1 = *(const uint32_t*)&wl[nr * XSB + k0 + 8];
                mma_f16(c[nf], ah, b0, b1);
                mma_f16acc(cc[nf], al, b0, b1);
                mma_f16acc(cc[nf], ah, d0, d1);
            }
        }
    }

    #pragma unroll
    for (int nf = 0; nf < 8; nf++) {
        __half2 c01 = *(__half2*)&cc[nf][0];
        __half2 c23 = *(__half2*)&cc[nf][1];
        c[nf][0] += __half2float(c01.x);
        c[nf][1] += __half2float(c01.y);
        c[nf][2] += __half2float(c23.x);
        c[nf][3] += __half2float(c23.y);
    }

    const int rowA = r0 + w * 16 + g, rowB = rowA + 8;
    if (p == 2) {
        #pragma unroll
        for (int nf = 0; nf < 8; nf++) {
            int c0 = nf * 8 + 2 * t;
            g_vh[c0 * SEQ + rowA]       = __float2half_rn(c[nf][0]);
            g_vh[(c0 + 1) * SEQ + rowA] = __float2half_rn(c[nf][1]);
            g_vh[c0 * SEQ + rowB]       = __float2half_rn(c[nf][2]);
            g_vh[(c0 + 1) * SEQ + rowB] = __float2half_rn(c[nf][3]);
        }
    } else {
        __half* dh = (p == 0) ? g_qh : g_kh;
        __half* dl = (p == 0) ? g_ql : g_kl;
        const float sc = (p == 0) ? QK_SCALE : 1.0f;
        #pragma unroll
        for (int nf = 0; nf < 8; nf++) {
            uint32_t hA, lA, hB, lB;
            fsplit2(c[nf][0] * sc, c[nf][1] * sc, hA, lA);
            fsplit2(c[nf][2] * sc, c[nf][3] * sc, hB, lB);
            int off = nf * 8 + 2 * t;
            *(uint32_t*)&dh[rowA * D + off] = hA;
            *(uint32_t*)&dl[rowA * D + off] = lA;
            *(uint32_t*)&dh[rowB * D + off] = hB;
            *(uint32_t*)&dl[rowB * D + off] = lB;
        }
    }
}

// ---------------------------------------------------------------------------
// Kernel 2: flash attention, M=32 per warp, j-paired S chains (8 independent
// accumulators per kc step) + nf-paired PV chains.  Q-lo fragments hoisted
// to once per unit.
// ---------------------------------------------------------------------------
__global__ __launch_bounds__(128, 2) void attn_kernel() {
    extern __shared__ __half smh[];
    __shared__ int sm_next;
    const uint32_t sbase = smem_u32(smh);

    const int tid = threadIdx.x, w = tid >> 5, lane = tid & 31;
    const int g = lane >> 2, t = lane & 3;

    const uint32_t lmo = (uint32_t)((lane & 7) * KST + (lane >> 3) * 8) * 2u;
    uint32_t qlo_lm[2];
    #pragma unroll
    for (int ms = 0; ms < 2; ms++)
        qlo_lm[ms] = sbase + (uint32_t)QLO_HALF * 2u
            + (uint32_t)((w * 32 + ms * 16 + (lane & 15)) * KST + (lane >> 4) * 8) * 2u;

    auto issue_tile = [&](int kt, int buf) {
        #pragma unroll
        for (int i = tid; i < 1536; i += 128) {
            int arr = i >> 9, rem = i & 511, r = rem >> 3, c8 = rem & 7;
            const __half* src;
            if      (arr == 0) src = &g_kh[(kt + r) * D + c8 * 8];
            else if (arr == 1) src = &g_kl[(kt + r) * D + c8 * 8];
            else               src = &g_vh[r * SEQ + kt + c8 * 8];
            uint32_t dst = sbase + (uint32_t)buf * BUFB
                         + (uint32_t)(arr * 64 * KST + r * KST + c8 * 8) * 2u;
            cp16(dst, src);
        }
        CP_COMMIT();
    };

    if (tid == 0) sm_next = (int)atomicAdd(&g_ctr, 1u);
    __syncthreads();
    int u = sm_next;
    if (u < TOTAL_UNITS) issue_tile((u & 15) * (TILES_PER_UNIT * BN), 0);

    while (u < TOTAL_UNITS) {
        const int rb = u >> 4, sl = u & 15;
        const int k0 = sl * (TILES_PER_UNIT * BN);

        // stage Q-lo tile (128 rows) into smem
        #pragma unroll
        for (int i = tid; i < 1024; i += 128) {
            int r = i >> 3, c8 = i & 7;
            *(uint4*)&smh[QLO_HALF + r * KST + c8 * 8] =
                *(const uint4*)&g_ql[(rb * 128 + r) * D + c8 * 8];
        }

        // Q-hi fragments for both m-subtiles (persistent)
        uint32_t qh[2][4][4];
        #pragma unroll
        for (int ms = 0; ms < 2; ms++) {
            const int rA = rb * 128 + w * 32 + ms * 16 + g, rB = rA + 8;
            #pragma unroll
            for (int kc = 0; kc < 4; kc++) {
                int kk0 = kc * 16 + 2 * t;
                qh[ms][kc][0] = *(const uint32_t*)&g_qh[rA * D + kk0];
                qh[ms][kc][1] = *(const uint32_t*)&g_qh[rB * D + kk0];
                qh[ms][kc][2] = *(const uint32_t*)&g_qh[rA * D + kk0 + 8];
                qh[ms][kc][3] = *(const uint32_t*)&g_qh[rB * D + kk0 + 8];
            }
        }
        __syncthreads();   // Q-lo staged before fragment loads

        // Q-lo fragments, loaded ONCE per unit
        uint32_t qlf[2][4][4];
        #pragma unroll
        for (int ms = 0; ms < 2; ms++)
            #pragma unroll
            for (int kc = 0; kc < 4; kc++)
                ldm_x4(qlf[ms][kc][0], qlf[ms][kc][1], qlf[ms][kc][2], qlf[ms][kc][3],
                       qlo_lm[ms] + (uint32_t)kc * 32u);

        float o[2][8][4];
        float m_a[2], m_b[2], l_a[2], l_b[2];
        #pragma unroll
        for (int ms = 0; ms < 2; ms++) {
            m_a[ms] = -INFINITY; m_b[ms] = -INFINITY;
            l_a[ms] = 0.0f; l_b[ms] = 0.0f;
            #pragma unroll
            for (int nf = 0; nf < 8; nf++)
                #pragma unroll
                for (int i = 0; i < 4; i++) o[ms][nf][i] = 0.0f;
        }

        int next_u = TOTAL_UNITS;

        for (int tt = 0; tt < TILES_PER_UNIT; tt++) {
            bool pref = true;
            if (tt + 1 < TILES_PER_UNIT) {
                issue_tile(k0 + (tt + 1) * BN, (tt + 1) & 1);
            } else {
                if (tid == 0) sm_next = (int)atomicAdd(&g_ctr, 1u);
                __syncthreads();
                next_u = sm_next;
                if (next_u < TOTAL_UNITS)
                    issue_tile((next_u & 15) * (TILES_PER_UNIT * BN), 0);
                else pref = false;
            }
            if (pref) { CP_WAIT1(); } else { CP_WAIT0(); }
            __syncthreads();

            const uint32_t tb = sbase + (uint32_t)(tt & 1) * BUFB;
            const uint32_t akh = tb + lmo;
            const uint32_t akl = akh + (uint32_t)(64 * KST) * 2u;
            const uint32_t avh = akl + (uint32_t)(64 * KST) * 2u;

            // ---- S = Q K^T : j-paired, 8 independent chains per kc ----
            float s_[2][8][4];
            #pragma unroll
            for (int ms = 0; ms < 2; ms++)
                #pragma unroll
                for (int j = 0; j < 8; j++)
                    #pragma unroll
                    for (int i = 0; i < 4; i++) s_[ms][j][i] = 0.0f;
            #pragma unroll
            for (int jp = 0; jp < 4; jp++) {
                const int j0 = 2 * jp, j1 = j0 + 1;
                const uint32_t rj0 = (uint32_t)(j0 * 8 * KST) * 2u;
                const uint32_t rj1 = (uint32_t)(j1 * 8 * KST) * 2u;
                uint32_t f0[8], f1[8];
                ldm_x4(f0[0], f0[1], f0[2], f0[3], akh + rj0);
                ldm_x4(f0[4], f0[5], f0[6], f0[7], akh + rj0 + 64);
                ldm_x4(f1[0], f1[1], f1[2], f1[3], akh + rj1);
                ldm_x4(f1[4], f1[5], f1[6], f1[7], akh + rj1 + 64);
                #pragma unroll
                for (int kc = 0; kc < 4; kc++) {
                    mma_f16(s_[0][j0], qh[0][kc],  f0[2 * kc], f0[2 * kc + 1]);
                    mma_f16(s_[0][j1], qh[0][kc],  f1[2 * kc], f1[2 * kc + 1]);
                    mma_f16(s_[1][j0], qh[1][kc],  f0[2 * kc], f0[2 * kc + 1]);
                    mma_f16(s_[1][j1], qh[1][kc],  f1[2 * kc], f1[2 * kc + 1]);
                    mma_f16(s_[0][j0], qlf[0][kc], f0[2 * kc], f0[2 * kc + 1]);
                    mma_f16(s_[0][j1], qlf[0][kc], f1[2 * kc], f1[2 * kc + 1]);
                    mma_f16(s_[1][j0], qlf[1][kc], f0[2 * kc], f0[2 * kc + 1]);
                    mma_f16(s_[1][j1], qlf[1][kc], f1[2 * kc], f1[2 * kc + 1]);
                }
                ldm_x4(f0[0], f0[1], f0[2], f0[3], akl + rj0);
                ldm_x4(f0[4], f0[5], f0[6], f0[7], akl + rj0 + 64);
                ldm_x4(f1[0], f1[1], f1[2], f1[3], akl + rj1);
                ldm_x4(f1[4], f1[5], f1[6], f1[7], akl + rj1 + 64);
                #pragma unroll
                for (int kc = 0; kc < 4; kc++) {
                    mma_f16(s_[0][j0], qh[0][kc], f0[2 * kc], f0[2 * kc + 1]);
                    mma_f16(s_[0][j1], qh[0][kc], f1[2 * kc], f1[2 * kc + 1]);
                    mma_f16(s_[1][j0], qh[1][kc], f0[2 * kc], f0[2 * kc + 1]);
                    mma_f16(s_[1][j1], qh[1][kc], f1[2 * kc], f1[2 * kc + 1]);
                }
            }

            // ---- online softmax (base-2) + pack P, per m-subtile ----
            uint32_t ah[2][4][4];
            #pragma unroll
            for (int ms = 0; ms < 2; ms++) {
                float mxa = -INFINITY, mxb = -INFINITY;
                #pragma unroll
                for (int j = 0; j < 8; j++) {
                    mxa = fmaxf(mxa, fmaxf(s_[ms][j][0], s_[ms][j][1]));
                    mxb = fmaxf(mxb, fmaxf(s_[ms][j][2], s_[ms][j][3]));
                }
                mxa = fmaxf(mxa, __shfl_xor_sync(0xffffffffu, mxa, 1));
                mxa = fmaxf(mxa, __shfl_xor_sync(0xffffffffu, mxa, 2));
                mxb = fmaxf(mxb, __shfl_xor_sync(0xffffffffu, mxb, 1));
                mxb = fmaxf(mxb, __shfl_xor_sync(0xffffffffu, mxb, 2));
                float mna = fmaxf(m_a[ms], mxa), mnb = fmaxf(m_b[ms], mxb);
                float ca = ex2(m_a[ms] - mna), cb = ex2(m_b[ms] - mnb);
                m_a[ms] = mna; m_b[ms] = mnb;
                float ra = 0.0f, rb2 = 0.0f;
                #pragma unroll
                for (int j = 0; j < 8; j++) {
                    s_[ms][j][0] = ex2(s_[ms][j][0] - mna);
                    s_[ms][j][1] = ex2(s_[ms][j][1] - mna);
                    s_[ms][j][2] = ex2(s_[ms][j][2] - mnb);
                    s_[ms][j][3] = ex2(s_[ms][j][3] - mnb);
                    ra  += s_[ms][j][0] + s_[ms][j][1];
                    rb2 += s_[ms][j][2] + s_[ms][j][3];
                }
                l_a[ms] = l_a[ms] * ca + ra;
                l_b[ms] = l_b[ms] * cb + rb2;
                #pragma unroll
                for (int nf = 0; nf < 8; nf++) {
                    o[ms][nf][0] *= ca; o[ms][nf][1] *= ca;
                    o[ms][nf][2] *= cb; o[ms][nf][3] *= cb;
                }
                #pragma unroll
                for (int kk = 0; kk < 4; kk++) {
                    ah[ms][kk][0] = pack_f16(s_[ms][2 * kk][0], s_[ms][2 * kk][1]);
                    ah[ms][kk][1] = pack_f16(s_[ms][2 * kk][2], s_[ms][2 * kk][3]);
                    ah[ms][kk][2] = pack_f16(s_[ms][2 * kk + 1][0], s_[ms][2 * kk + 1][1]);
                    ah[ms][kk][3] = pack_f16(s_[ms][2 * kk + 1][2], s_[ms][2 * kk + 1][3]);
                }
            }

            // ---- O += P V : nf-paired, 4 independent chains per kk ----
            #pragma unroll
            for (int np = 0; np < 4; np++) {
                const int n0 = 2 * np, n1 = n0 + 1;
                const uint32_t rn0 = (uint32_t)(n0 * 8 * KST) * 2u;
                const uint32_t rn1 = (uint32_t)(n1 * 8 * KST) * 2u;
                uint32_t f0[8], f1[8];
                ldm_x4(f0[0], f0[1], f0[2], f0[3], avh + rn0);
                ldm_x4(f0[4], f0[5], f0[6], f0[7], avh + rn0 + 64);
                ldm_x4(f1[0], f1[1], f1[2], f1[3], avh + rn1);
                ldm_x4(f1[4], f1[5], f1[6], f1[7], avh + rn1 + 64);
                #pragma unroll
                for (int kk = 0; kk < 4; kk++) {
                    mma_f16(o[0][n0], ah[0][kk], f0[2 * kk], f0[2 * kk + 1]);
                    mma_f16(o[0][n1], ah[0][kk], f1[2 * kk], f1[2 * kk + 1]);
                    mma_f16(o[1][n0], ah[1][kk], f0[2 * kk], f0[2 * kk + 1]);
                    mma_f16(o[1][n1], ah[1][kk], f1[2 * kk], f1[2 * kk + 1]);
                }
            }
            __syncthreads();
        }

        // ---- unit epilogue (per m-subtile) ----
        #pragma unroll
        for (int ms = 0; ms < 2; ms++) {
            float la = l_a[ms] + __shfl_xor_sync(0xffffffffu, l_a[ms], 1);
            la += __shfl_xor_sync(0xffffffffu, la, 2);
            float lb = l_b[ms] + __shfl_xor_sync(0xffffffffu, l_b[ms], 1);
            lb += __shfl_xor_sync(0xffffffffu, lb, 2);

            const int rowA = rb * 128 + w * 32 + ms * 16 + g, rowB = rowA + 8;
            #pragma unroll
            for (int nf = 0; nf < 8; nf++) {
                *(float2*)&g_po[sl][rowA * D + nf * 8 + 2 * t] =
                    make_float2(o[ms][nf][0], o[ms][nf][1]);
                *(float2*)&g_po[sl][rowB * D + nf * 8 + 2 * t] =
                    make_float2(o[ms][nf][2], o[ms][nf][3]);
            }
            if (t == 0) {
                g_pm[sl][rowA] = m_a[ms]; g_pl[sl][rowA] = la;
                g_pm[sl][rowB] = m_b[ms]; g_pl[sl][rowB] = lb;
            }
        }
        u = next_u;
    }
}

// ---------------------------------------------------------------------------
// Kernel 3: combine the 16 KV slices, float4-vectorized.
// ---------------------------------------------------------------------------
__global__ __launch_bounds__(256) void combine_kernel(float* __restrict__ out) {
    __shared__ float ws[16][NSPLIT];
    const int tid = threadIdx.x;
    const int r0 = blockIdx.x * 16;

    if (tid < 16) {
        int r = r0 + tid;
        float M = -INFINITY;
        #pragma unroll
        for (int i = 0; i < NSPLIT; i++) M = fmaxf(M, g_pm[i][r]);
        float wv[NSPLIT];
        float den = 0.0f;
        #pragma unroll
        for (int i = 0; i < NSPLIT; i++) {
            wv[i] = ex2(g_pm[i][r] - M);
            den += g_pl[i][r] * wv[i];
        }
        float inv = __frcp_rn(den);
        #pragma unroll
        for (int i = 0; i < NSPLIT; i++) ws[tid][i] = wv[i] * inv;
    }
    __syncthreads();

    const int idx4 = (blockIdx.x * 256 + tid) * 4;
    const int rloc = (idx4 >> 6) & 15;
    float4 acc = make_float4(0.f, 0.f, 0.f, 0.f);
    #pragma unroll
    for (int i = 0; i < NSPLIT; i++) {
        float4 v = *(const float4*)&g_po[i][idx4];
        float wgt = ws[rloc][i];
        acc.x += v.x * wgt; acc.y += v.y * wgt;
        acc.z += v.z * wgt; acc.w += v.w * wgt;
    }
    *(float4*)&out[idx4] = acc;
}

// ---------------------------------------------------------------------------
extern "C" void kernel_launch(void* const* d_in, const int* in_sizes, int n_in,
                              void* d_out, int out_size) {
    const float* x  = (const float*)d_in[0];
    const float* Wq = (const float*)d_in[1];
    const float* Wk = (const float*)d_in[2];
    const float* Wv = (const float*)d_in[3];
    float* out = (float*)d_out;

    cudaFuncSetAttribute(qkv_kernel,
                         cudaFuncAttributeMaxDynamicSharedMemorySize, QKV_SMEM);
    cudaFuncSetAttribute(attn_kernel,
                         cudaFuncAttributeMaxDynamicSharedMemorySize, ATT_SMEM);

    zero_ctr_kernel<<<1, 1>>>();
    prep_kernel<<<(3 * D * DIN) / 256, 256>>>(Wq, Wk, Wv);
    qkv_kernel<<<dim3(SEQ / 128, 3), 256, QKV_SMEM>>>(x);
    attn_kernel<<<GRID_ATTN, 128, ATT_SMEM>>>();
    combine_kernel<<<(SEQ * D) / 1024, 256>>>(out);
}